// round 12
// baseline (speedup 1.0000x reference)
#include <cuda_runtime.h>
#include <cuda_bf16.h>
#include <cstdint>

#define N_MAX   4096
#define D_MAX   2048
#define MARGIN  0.3f
#define NPART   16

__device__ float           g_sq[N_MAX];
__device__ unsigned        g_max2[N_MAX];  // max clamped dist^2, same-class (uint-encoded fp32 >= 0)
__device__ unsigned        g_min2[N_MAX];  // min clamped dist^2, zero_neg   (uint-encoded fp32 >= 0)
__device__ int             g_flag;
__device__ int             g_done;
__device__ float           g_partial[NPART];
__device__ __nv_bfloat16   g_xb[(size_t)N_MAX * D_MAX];   // bf16 copy of inputs (16 MB)

// ======================= prep: norms (fp32 exact) + bf16 convert + flag =====
__global__ void prep_kernel(const float* __restrict__ x, const int* __restrict__ tgt,
                            int n, int d) {
    int warp = (blockIdx.x * blockDim.x + threadIdx.x) >> 5;
    int lane = threadIdx.x & 31;

    if (warp < n) {
        const float4* row = (const float4*)(x + (size_t)warp * d);
        uint4* orow = (uint4*)(g_xb + (size_t)warp * d);
        int nv = d >> 3;
        float s = 0.f;
        for (int v = lane; v < nv; v += 32) {
            float4 f0 = row[v * 2];
            float4 f1 = row[v * 2 + 1];
            s += f0.x * f0.x + f0.y * f0.y + f0.z * f0.z + f0.w * f0.w;
            s += f1.x * f1.x + f1.y * f1.y + f1.z * f1.z + f1.w * f1.w;
            __nv_bfloat162 h0 = __floats2bfloat162_rn(f0.x, f0.y);
            __nv_bfloat162 h1 = __floats2bfloat162_rn(f0.z, f0.w);
            __nv_bfloat162 h2 = __floats2bfloat162_rn(f1.x, f1.y);
            __nv_bfloat162 h3 = __floats2bfloat162_rn(f1.z, f1.w);
            uint4 o;
            o.x = *(uint32_t*)&h0; o.y = *(uint32_t*)&h1;
            o.z = *(uint32_t*)&h2; o.w = *(uint32_t*)&h3;
            orow[v] = o;
        }
        #pragma unroll
        for (int o = 16; o; o >>= 1) s += __shfl_xor_sync(0xffffffffu, s, o);
        if (lane == 0) {
            g_sq[warp]   = s;
            g_max2[warp] = 0u;
            g_min2[warp] = 0x7f800000u;
        }
    }

    if (blockIdx.x == 0) {
        int t0 = tgt[0];
        int loc = 0;
        for (int j = threadIdx.x; j < n; j += blockDim.x) {
            int tj = tgt[j];
            if ((t0 != tj) && (t0 == 0 || tj == 0)) loc = 1;
        }
        int f = __syncthreads_or(loc);
        if (threadIdx.x == 0) { g_flag = f; g_done = 0; }
    }
}

// ======================= PTX helpers (baseline ISA only) ====================
__device__ __forceinline__ uint32_t smem_u32(const void* p) {
    uint32_t a;
    asm("{ .reg .u64 t; cvta.to.shared.u64 t, %1; cvt.u32.u64 %0, t; }" : "=r"(a) : "l"(p));
    return a;
}
#define CP16(sa, ga) \
    asm volatile("cp.async.cg.shared.global [%0], [%1], 16;" :: "r"(sa), "l"(ga) : "memory")
#define CP_COMMIT()  asm volatile("cp.async.commit_group;" ::: "memory")
#define CP_WAIT1()   asm volatile("cp.async.wait_group 1;" ::: "memory")

#define LDSM_X4(r, a) \
    asm volatile("ldmatrix.sync.aligned.m8n8.x4.shared.b16 {%0,%1,%2,%3}, [%4];" \
        : "=r"((r)[0]), "=r"((r)[1]), "=r"((r)[2]), "=r"((r)[3]) : "r"(a))
#define LDSM_X2(r, a) \
    asm volatile("ldmatrix.sync.aligned.m8n8.x2.shared.b16 {%0,%1}, [%2];" \
        : "=r"((r)[0]), "=r"((r)[1]) : "r"(a))

#define MMA16816(c, a, b) \
    asm volatile("mma.sync.aligned.m16n8k16.row.col.f32.bf16.bf16.f32 " \
        "{%0,%1,%2,%3},{%4,%5,%6,%7},{%8,%9},{%0,%1,%2,%3};" \
        : "+f"((c)[0]), "+f"((c)[1]), "+f"((c)[2]), "+f"((c)[3]) \
        : "r"((a)[0]), "r"((a)[1]), "r"((a)[2]), "r"((a)[3]), "r"((b)[0]), "r"((b)[1]))

// ======================= bf16 mma.sync fused GEMM + reduction + loss ========
// Block tile 128x128, 8 warps in 2x4 grid (warp tile 64x32), K stage = 32.
// 3 CTAs/SM: three independent barrier domains per SM to fill issue bubbles.
#define BM    128
#define BKE   32                 // bf16 elems per K stage (64 B rows)
#define SROW  80                 // smem row stride (bytes) -> conflict-free ldmatrix
#define STG_M (BM * SROW)        // 10240 per matrix per stage
#define STG   (2 * STG_M)        // 20480 per stage
#define NSTG  3
#define SM_RED   (NSTG * STG)              // 61440
#define SM_TOTAL (SM_RED + 2048)           // 63488

__global__ void __launch_bounds__(256, 3)
gemm_mma_kernel(const int* __restrict__ tgt, float* __restrict__ out,
                int n, int d, int nb) {
    extern __shared__ char smem[];
    const uint32_t smemu = smem_u32(smem);
    const int tid  = threadIdx.x;
    const int wid  = tid >> 5;
    const int lane = tid & 31;

    // triangular tile map (bi <= bj)
    int p = blockIdx.x, bi = 0, rem = p;
    while (rem >= nb - bi) { rem -= (nb - bi); bi++; }
    int bj = bi + rem;
    const int iBase = bi * BM;
    const int jBase = bj * BM;

    const int nkt = d / BKE;     // 64 stages
    const size_t dB = (size_t)d * 2;              // row stride in bytes
    const char* pA = (const char*)(g_xb) + (size_t)iBase * dB;
    const char* pB = (const char*)(g_xb) + (size_t)jBase * dB;

    // warp tiling: 2 (M) x 4 (N) warps, warp tile 64x32
    const int mWarp = (wid >> 2) * 64;
    const int nWarp = (wid & 3) * 32;

    float acc[4][4][4];
    #pragma unroll
    for (int mt = 0; mt < 4; mt++)
        #pragma unroll
        for (int nt = 0; nt < 4; nt++)
            #pragma unroll
            for (int e = 0; e < 4; e++) acc[mt][nt][e] = 0.f;

    // cp.async: 128 rows x 4 chunks of 16B per matrix = 512 tasks, 2/thread.
    // Addresses recomputed per issue (rematerializable -> low reg pressure).
    auto issue = [&](int s, int kt) {
        uint32_t aS = smemu + s * STG;
        uint32_t bS = aS + STG_M;
        int koff = kt * 64;
        #pragma unroll
        for (int t = 0; t < 2; t++) {
            int chunk = tid + t * 256;
            int r = chunk >> 2;
            int c = (chunk & 3) * 16;
            uint32_t so = r * SROW + c;
            size_t go = (size_t)r * dB + koff + c;
            CP16(aS + so, pA + go);
            CP16(bS + so, pB + go);
        }
    };

    issue(0, 0); CP_COMMIT();
    issue(1, 1); CP_COMMIT();

    const uint32_t aRowOff = (mWarp + (lane & 15)) * SROW + ((lane >> 4) & 1) * 16;
    const uint32_t bRowOff = (nWarp + (lane & 7))  * SROW + ((lane >> 3) & 1) * 16;

    for (int kt = 0; kt < nkt; kt++) {
        CP_WAIT1();
        __syncthreads();
        if (kt + 2 < nkt) { issue((kt + 2) % NSTG, kt + 2); }
        CP_COMMIT();

        int s = kt % NSTG;
        uint32_t aS = smemu + s * STG;
        uint32_t bS = aS + STG_M;
        #pragma unroll
        for (int kk = 0; kk < 2; kk++) {
            uint32_t rb[4][2];
            #pragma unroll
            for (int nt = 0; nt < 4; nt++)
                LDSM_X2(rb[nt], bS + bRowOff + nt * 8 * SROW + kk * 32);
            #pragma unroll
            for (int mt = 0; mt < 4; mt++) {
                uint32_t ra[4];
                LDSM_X4(ra, aS + aRowOff + mt * 16 * SROW + kk * 32);
                #pragma unroll
                for (int nt = 0; nt < 4; nt++)
                    MMA16816(acc[mt][nt], ra, rb[nt]);
            }
        }
    }
    __syncthreads();

    // --- epilogue: dist^2 + masked max/min reductions ------------------------
    // acc fragment (m16n8): e0:(r,c) e1:(r,c+1) e2:(r+8,c) e3:(r+8,c+1)
    float sqi[8], sqj[8];
    int   ti[8], tj[8];
    #pragma unroll
    for (int mt = 0; mt < 4; mt++)
        #pragma unroll
        for (int h = 0; h < 2; h++) {
            int gi = iBase + mWarp + mt * 16 + (lane >> 2) + h * 8;
            sqi[mt * 2 + h] = g_sq[gi];
            ti[mt * 2 + h]  = tgt[gi];
        }
    #pragma unroll
    for (int nt = 0; nt < 4; nt++)
        #pragma unroll
        for (int pp = 0; pp < 2; pp++) {
            int gj = jBase + nWarp + nt * 8 + 2 * (lane & 3) + pp;
            sqj[nt * 2 + pp] = g_sq[gj];
            tj[nt * 2 + pp]  = tgt[gj];
        }

    const unsigned UINF = 0x7f800000u;
    unsigned rmax[8], rmin[8], cmax[8], cmin[8];
    #pragma unroll
    for (int q = 0; q < 8; q++) { rmax[q] = 0u; rmin[q] = UINF; cmax[q] = 0u; cmin[q] = UINF; }

    #pragma unroll
    for (int mt = 0; mt < 4; mt++)
        #pragma unroll
        for (int nt = 0; nt < 4; nt++)
            #pragma unroll
            for (int e = 0; e < 4; e++) {
                int h = e >> 1, pp = e & 1;
                int ri = mt * 2 + h, cj = nt * 2 + pp;
                float d2 = fmaxf(sqi[ri] + sqj[cj] - 2.f * acc[mt][nt][(h << 1) | pp], 1e-12f);
                unsigned b = __float_as_uint(d2);
                bool same = (ti[ri] == tj[cj]);
                bool zn   = !same && (ti[ri] == 0 || tj[cj] == 0);
                if (same) { rmax[ri] = max(rmax[ri], b); cmax[cj] = max(cmax[cj], b); }
                if (zn)   { rmin[ri] = min(rmin[ri], b); cmin[cj] = min(cmin[cj], b); }
            }

    unsigned* sredmax = (unsigned*)(smem + SM_RED);
    unsigned* sredmin = sredmax + 256;
    sredmax[tid] = 0u;
    sredmin[tid] = UINF;
    __syncthreads();

    #pragma unroll
    for (int mt = 0; mt < 4; mt++)
        #pragma unroll
        for (int h = 0; h < 2; h++) {
            int q = mt * 2 + h;
            int loc = mWarp + mt * 16 + (lane >> 2) + h * 8;
            if (rmax[q]) atomicMax(&sredmax[loc], rmax[q]);
            if (rmin[q] != UINF) atomicMin(&sredmin[loc], rmin[q]);
        }
    #pragma unroll
    for (int nt = 0; nt < 4; nt++)
        #pragma unroll
        for (int pp = 0; pp < 2; pp++) {
            int q = nt * 2 + pp;
            int loc = 128 + nWarp + nt * 8 + 2 * (lane & 3) + pp;
            if (cmax[q]) atomicMax(&sredmax[loc], cmax[q]);
            if (cmin[q] != UINF) atomicMin(&sredmin[loc], cmin[q]);
        }
    __syncthreads();

    int row = (tid < 128) ? (iBase + tid) : (jBase + (tid - 128));
    if (sredmax[tid]) atomicMax(&g_max2[row], sredmax[tid]);
    if (sredmin[tid] != UINF) atomicMin(&g_min2[row], sredmin[tid]);

    // --- last-CTA tail: full loss reduction ----------------------------------
    __threadfence();
    __shared__ int amlast;
    if (tid == 0) amlast = (atomicAdd(&g_done, 1) == (int)gridDim.x - 1);
    __syncthreads();
    if (amlast) {
        int flag = g_flag;
        float s = 0.f;
        for (int i = tid; i < n; i += 256) {
            float ap = sqrtf(__uint_as_float(__ldcg(&g_max2[i])));
            float an = flag ? sqrtf(__uint_as_float(__ldcg(&g_min2[i]))) : 0.f;
            s += fmaxf(ap - an + MARGIN, 0.f);   // min2==+inf & flag -> -inf -> 0
        }
        float* ssum = (float*)(smem + SM_RED);
        ssum[tid] = s;
        __syncthreads();
        #pragma unroll
        for (int o = 128; o; o >>= 1) {
            if (tid < o) ssum[tid] += ssum[tid + o];
            __syncthreads();
        }
        if (tid == 0) out[0] = ssum[0] / (float)n;
    }
}

// ======================= legacy fp32 fallback (proven) ======================
#define LT    128
#define LKT   16
#define LPAD  4
__global__ void __launch_bounds__(256, 2)
gemm_reduce_legacy(const float* __restrict__ x, const int* __restrict__ tgt,
                   int n, int d, int nb) {
    int p = blockIdx.x, bi = 0, rem = p;
    while (rem >= nb - bi) { rem -= (nb - bi); bi++; }
    int bj = bi + rem;
    const int iBase = bi * LT;
    const int jBase = bj * LT;
    const int tid = threadIdx.x;
    const int tx = tid & 15;
    const int ty = tid >> 4;

    __shared__ float As[LKT][LT + LPAD];
    __shared__ float Bs[LKT][LT + LPAD];
    __shared__ unsigned sredmax[2 * LT];
    __shared__ unsigned sredmin[2 * LT];

    float acc[8][8];
    #pragma unroll
    for (int r = 0; r < 8; r++)
        #pragma unroll
        for (int c = 0; c < 8; c++) acc[r][c] = 0.f;

    const int nkt = d / LKT;
    float4 pa[2], pb[2];
    #pragma unroll
    for (int u = 0; u < 2; u++) {
        int idx = tid + u * 256, r = idx >> 2, c4 = idx & 3;
        pa[u] = *(const float4*)(x + (size_t)(iBase + r) * d + c4 * 4);
        pb[u] = *(const float4*)(x + (size_t)(jBase + r) * d + c4 * 4);
    }
    #pragma unroll
    for (int u = 0; u < 2; u++) {
        int idx = tid + u * 256, r = idx >> 2, c4 = idx & 3;
        As[c4*4+0][r]=pa[u].x; As[c4*4+1][r]=pa[u].y; As[c4*4+2][r]=pa[u].z; As[c4*4+3][r]=pa[u].w;
        Bs[c4*4+0][r]=pb[u].x; Bs[c4*4+1][r]=pb[u].y; Bs[c4*4+2][r]=pb[u].z; Bs[c4*4+3][r]=pb[u].w;
    }
    __syncthreads();
    for (int kt = 0; kt < nkt; kt++) {
        if (kt + 1 < nkt) {
            int k0 = (kt + 1) * LKT;
            #pragma unroll
            for (int u = 0; u < 2; u++) {
                int idx = tid + u * 256, r = idx >> 2, c4 = idx & 3;
                pa[u] = *(const float4*)(x + (size_t)(iBase + r) * d + k0 + c4 * 4);
                pb[u] = *(const float4*)(x + (size_t)(jBase + r) * d + k0 + c4 * 4);
            }
        }
        #pragma unroll
        for (int k = 0; k < LKT; k++) {
            float a[8], b[8];
            *(float4*)(a)   = *(const float4*)&As[k][ty*8];
            *(float4*)(a+4) = *(const float4*)&As[k][ty*8+4];
            *(float4*)(b)   = *(const float4*)&Bs[k][tx*8];
            *(float4*)(b+4) = *(const float4*)&Bs[k][tx*8+4];
            #pragma unroll
            for (int r = 0; r < 8; r++)
                #pragma unroll
                for (int c = 0; c < 8; c++) acc[r][c] += a[r] * b[c];
        }
        __syncthreads();
        if (kt + 1 < nkt) {
            #pragma unroll
            for (int u = 0; u < 2; u++) {
                int idx = tid + u * 256, r = idx >> 2, c4 = idx & 3;
                As[c4*4+0][r]=pa[u].x; As[c4*4+1][r]=pa[u].y; As[c4*4+2][r]=pa[u].z; As[c4*4+3][r]=pa[u].w;
                Bs[c4*4+0][r]=pb[u].x; Bs[c4*4+1][r]=pb[u].y; Bs[c4*4+2][r]=pb[u].z; Bs[c4*4+3][r]=pb[u].w;
            }
            __syncthreads();
        }
    }

    float sqi[8], sqj[8];
    int ti8[8], tj8[8];
    #pragma unroll
    for (int r = 0; r < 8; r++) { int i = iBase + ty*8 + r; sqi[r] = g_sq[i]; ti8[r] = tgt[i]; }
    #pragma unroll
    for (int c = 0; c < 8; c++) { int j = jBase + tx*8 + c; sqj[c] = g_sq[j]; tj8[c] = tgt[j]; }

    const float INF = __uint_as_float(0x7f800000u);
    float rmax[8], rmin[8], cmax[8], cmin[8];
    #pragma unroll
    for (int r = 0; r < 8; r++) { rmax[r] = 0.f; rmin[r] = INF; }
    #pragma unroll
    for (int c = 0; c < 8; c++) { cmax[c] = 0.f; cmin[c] = INF; }
    #pragma unroll
    for (int r = 0; r < 8; r++)
        #pragma unroll
        for (int c = 0; c < 8; c++) {
            float d2 = fmaxf(sqi[r] + sqj[c] - 2.f * acc[r][c], 1e-12f);
            bool same = (ti8[r] == tj8[c]);
            bool zn = !same && (ti8[r] == 0 || tj8[c] == 0);
            if (same) { rmax[r] = fmaxf(rmax[r], d2); cmax[c] = fmaxf(cmax[c], d2); }
            if (zn)   { rmin[r] = fminf(rmin[r], d2); cmin[c] = fminf(cmin[c], d2); }
        }
    sredmax[tid] = 0u; sredmin[tid] = 0x7f800000u;
    __syncthreads();
    #pragma unroll
    for (int r = 0; r < 8; r++) {
        atomicMax(&sredmax[ty*8+r], __float_as_uint(rmax[r]));
        atomicMin(&sredmin[ty*8+r], __float_as_uint(rmin[r]));
    }
    #pragma unroll
    for (int c = 0; c < 8; c++) {
        atomicMax(&sredmax[LT + tx*8+c], __float_as_uint(cmax[c]));
        atomicMin(&sredmin[LT + tx*8+c], __float_as_uint(cmin[c]));
    }
    __syncthreads();
    int row = (tid < LT) ? (iBase + tid) : (jBase + (tid - LT));
    atomicMax(&g_max2[row], sredmax[tid]);
    atomicMin(&g_min2[row], sredmin[tid]);
}

// ======================= legacy finalize (fallback path only) ===============
__global__ void partial_kernel(const int* __restrict__ tgt, int n) {
    __shared__ float ssum[256];
    int flag = g_flag;
    int chunk = (n + NPART - 1) / NPART;
    int beg = blockIdx.x * chunk;
    int end = min(beg + chunk, n);
    float s = 0.f;
    for (int i = beg + (int)threadIdx.x; i < end; i += blockDim.x) {
        float ap = sqrtf(__uint_as_float(g_max2[i]));
        float an = flag ? sqrtf(__uint_as_float(g_min2[i])) : 0.f;
        s += fmaxf(ap - an + MARGIN, 0.f);
    }
    ssum[threadIdx.x] = s;
    __syncthreads();
    #pragma unroll
    for (int o = 128; o; o >>= 1) {
        if (threadIdx.x < o) ssum[threadIdx.x] += ssum[threadIdx.x + o];
        __syncthreads();
    }
    if (threadIdx.x == 0) g_partial[blockIdx.x] = ssum[0];
}

__global__ void final_kernel(float* __restrict__ out, int n) {
    if (threadIdx.x == 0) {
        float s = 0.f;
        #pragma unroll
        for (int b = 0; b < NPART; b++) s += g_partial[b];
        out[0] = s / (float)n;
    }
}

// ======================= host launcher ======================================
extern "C" void kernel_launch(void* const* d_in, const int* in_sizes, int n_in,
                              void* d_out, int out_size) {
    const float* x   = (const float*)d_in[0];
    const int*   tgt = (const int*)d_in[1];   // int32 (JAX x64 disabled)
    int n = in_sizes[1];
    int d = in_sizes[0] / n;

    prep_kernel<<<(n + 7) / 8, 256>>>(x, tgt, n, d);

    bool tc_ok = (n % BM == 0) && (d % BKE == 0) && (d / BKE >= 2) &&
                 ((size_t)n * d <= (size_t)N_MAX * D_MAX);
    if (tc_ok) {
        static bool attr_set = false;
        if (!attr_set) {
            cudaFuncSetAttribute(gemm_mma_kernel,
                                 cudaFuncAttributeMaxDynamicSharedMemorySize, SM_TOTAL);
            attr_set = true;
        }
        int nb = n / BM;
        int nblocks = nb * (nb + 1) / 2;
        gemm_mma_kernel<<<nblocks, 256, SM_TOTAL>>>(tgt, (float*)d_out, n, d, nb);
    } else {
        int nb = n / LT;
        int nblocks = nb * (nb + 1) / 2;
        gemm_reduce_legacy<<<nblocks, 256>>>(x, tgt, n, d, nb);
        partial_kernel<<<NPART, 256>>>(tgt, n);
        final_kernel<<<1, 32>>>((float*)d_out, n);
    }
}

// round 13
// speedup vs baseline: 3.3377x; 3.3377x over previous
#include <cuda_runtime.h>
#include <cuda_bf16.h>
#include <cstdint>

#define N_MAX   4096
#define D_MAX   2048
#define NCLS    32
#define MARGIN  0.3f
#define NPART   16

__device__ float           g_sq[N_MAX];      // permuted-space row sumsq
__device__ unsigned        g_max2[N_MAX];    // permuted-space reductions
__device__ unsigned        g_min2[N_MAX];
__device__ int             g_flag;
__device__ int             g_done;
__device__ int             g_perm[N_MAX];
__device__ int             g_tgtp[N_MAX];    // permuted targets
__device__ int2            g_tiles[2112];
__device__ int             g_ntiles;
__device__ float           g_partial[NPART];
__device__ __nv_bfloat16   g_xb[(size_t)N_MAX * D_MAX];  // permuted bf16 rows

// ============ sort: histogram + scan + scatter + flag + tile table ==========
__global__ void sort_kernel(const int* __restrict__ tgt, int n) {
    __shared__ int scnt[NCLS], soff[NCLS], sfill[NCLS];
    int tid = threadIdx.x;
    if (tid < NCLS) scnt[tid] = 0;
    __syncthreads();
    for (int i = tid; i < n; i += blockDim.x) atomicAdd(&scnt[tgt[i]], 1);
    __syncthreads();
    if (tid == 0) {
        int acc = 0;
        for (int c = 0; c < NCLS; c++) { soff[c] = acc; sfill[c] = acc; acc += scnt[c]; }
    }
    __syncthreads();
    for (int i = tid; i < n; i += blockDim.x) {
        int c = tgt[i];
        int pos = atomicAdd(&sfill[c], 1);
        g_perm[pos] = i;
        g_tgtp[pos] = c;
    }
    if (tid == 0) {
        int t0 = tgt[0];
        int c0 = scnt[0];
        g_flag = (t0 == 0) ? ((n - c0) > 0 ? 1 : 0) : (c0 > 0 ? 1 : 0);
        g_done = 0;
        // tile table: per-class triangular diag tiles + class0 x nonzero strip
        int nt = 0;
        int nb = (n + 127) >> 7;
        for (int c = 0; c < NCLS; c++) {
            int off = soff[c], cnt = scnt[c];
            int t = (cnt + 127) >> 7;
            for (int a = 0; a < t; a++)
                for (int b = a; b < t; b++)
                    g_tiles[nt++] = make_int2(off + a * 128, off + b * 128);
        }
        int ti0 = (c0 + 127) >> 7;                 // class-0 row tiles (offset 0)
        for (int a = 0; a < ti0; a++)
            for (int jb = (c0 >> 7); jb < nb; jb++)
                g_tiles[nt++] = make_int2(a * 128, jb * 128);
        g_ntiles = nt;
    }
}

// ============ prep: permuted gather, fp32 norms, bf16 convert, init =========
__global__ void prep_kernel(const float* __restrict__ x, int n, int d) {
    int p = (blockIdx.x * blockDim.x + threadIdx.x) >> 5;
    int lane = threadIdx.x & 31;
    if (p >= n) return;
    int src = g_perm[p];
    const float4* row = (const float4*)(x + (size_t)src * d);
    uint4* orow = (uint4*)(g_xb + (size_t)p * d);
    int nv = d >> 3;
    float s = 0.f;
    for (int v = lane; v < nv; v += 32) {
        float4 f0 = row[v * 2];
        float4 f1 = row[v * 2 + 1];
        s += f0.x * f0.x + f0.y * f0.y + f0.z * f0.z + f0.w * f0.w;
        s += f1.x * f1.x + f1.y * f1.y + f1.z * f1.z + f1.w * f1.w;
        __nv_bfloat162 h0 = __floats2bfloat162_rn(f0.x, f0.y);
        __nv_bfloat162 h1 = __floats2bfloat162_rn(f0.z, f0.w);
        __nv_bfloat162 h2 = __floats2bfloat162_rn(f1.x, f1.y);
        __nv_bfloat162 h3 = __floats2bfloat162_rn(f1.z, f1.w);
        uint4 o;
        o.x = *(uint32_t*)&h0; o.y = *(uint32_t*)&h1;
        o.z = *(uint32_t*)&h2; o.w = *(uint32_t*)&h3;
        orow[v] = o;
    }
    #pragma unroll
    for (int o = 16; o; o >>= 1) s += __shfl_xor_sync(0xffffffffu, s, o);
    if (lane == 0) {
        g_sq[p]   = s;
        g_max2[p] = 0u;
        g_min2[p] = 0x7f800000u;
    }
}

// ======================= PTX helpers (baseline ISA only) ====================
__device__ __forceinline__ uint32_t smem_u32(const void* p) {
    uint32_t a;
    asm("{ .reg .u64 t; cvta.to.shared.u64 t, %1; cvt.u32.u64 %0, t; }" : "=r"(a) : "l"(p));
    return a;
}
#define CP16(sa, ga) \
    asm volatile("cp.async.cg.shared.global [%0], [%1], 16;" :: "r"(sa), "l"(ga) : "memory")
#define CP_COMMIT()  asm volatile("cp.async.commit_group;" ::: "memory")
#define CP_WAIT1()   asm volatile("cp.async.wait_group 1;" ::: "memory")
#define CP_WAIT0()   asm volatile("cp.async.wait_group 0;" ::: "memory")

#define LDSM_X4(r, a) \
    asm volatile("ldmatrix.sync.aligned.m8n8.x4.shared.b16 {%0,%1,%2,%3}, [%4];" \
        : "=r"((r)[0]), "=r"((r)[1]), "=r"((r)[2]), "=r"((r)[3]) : "r"(a))
#define LDSM_X2(r, a) \
    asm volatile("ldmatrix.sync.aligned.m8n8.x2.shared.b16 {%0,%1}, [%2];" \
        : "=r"((r)[0]), "=r"((r)[1]) : "r"(a))

#define MMA16816(c, a, b) \
    asm volatile("mma.sync.aligned.m16n8k16.row.col.f32.bf16.bf16.f32 " \
        "{%0,%1,%2,%3},{%4,%5,%6,%7},{%8,%9},{%0,%1,%2,%3};" \
        : "+f"((c)[0]), "+f"((c)[1]), "+f"((c)[2]), "+f"((c)[3]) \
        : "r"((a)[0]), "r"((a)[1]), "r"((a)[2]), "r"((a)[3]), "r"((b)[0]), "r"((b)[1]))

// ============ sparse-tile bf16 GEMM + masked reductions + loss tail =========
#define BM    128
#define BKE   64                 // bf16 elems per K stage (128 B rows)
#define SROW  144
#define STG_M (BM * SROW)        // 18432
#define STG   (2 * STG_M)        // 36864
#define NSTG  3
#define SM_RED   (NSTG * STG)              // 110592
#define SM_TOTAL (SM_RED + 2048)           // 112640

__global__ void __launch_bounds__(256, 2)
gemm_mma_kernel(float* __restrict__ out, int n, int d) {
    extern __shared__ char smem[];
    const uint32_t smemu = smem_u32(smem);
    const int tid  = threadIdx.x;
    const int wid  = tid >> 5;
    const int lane = tid & 31;
    const int nkt  = d / BKE;
    const size_t dB = (size_t)d * 2;

    const int mWarp = (wid >> 2) * 64;
    const int nWarp = (wid & 3) * 32;
    const uint32_t aRowOff = (mWarp + (lane & 15)) * SROW + ((lane >> 4) & 1) * 16;
    const uint32_t bRowOff = (nWarp + (lane & 7))  * SROW + ((lane >> 3) & 1) * 16;
    const unsigned UINF = 0x7f800000u;

    int ntiles = g_ntiles;
    for (int tix = blockIdx.x; tix < ntiles; tix += gridDim.x) {
        int2 tile = g_tiles[tix];
        const int iBase = tile.x;
        const int jBase = tile.y;

        float acc[4][4][4];
        #pragma unroll
        for (int mt = 0; mt < 4; mt++)
            #pragma unroll
            for (int nt = 0; nt < 4; nt++)
                #pragma unroll
                for (int e = 0; e < 4; e++) acc[mt][nt][e] = 0.f;

        auto issue = [&](int s, int kt) {
            uint32_t aS = smemu + s * STG;
            uint32_t bS = aS + STG_M;
            int koff = kt * 128;
            #pragma unroll
            for (int t = 0; t < 4; t++) {
                int chunk = tid + t * 256;
                int r = chunk >> 3;
                int c = (chunk & 7) * 16;
                uint32_t so = r * SROW + c;
                int ri = min(iBase + r, n - 1);
                int rj = min(jBase + r, n - 1);
                CP16(aS + so, (const char*)g_xb + (size_t)ri * dB + koff + c);
                CP16(bS + so, (const char*)g_xb + (size_t)rj * dB + koff + c);
            }
        };

        issue(0, 0); CP_COMMIT();
        issue(1, 1); CP_COMMIT();

        for (int kt = 0; kt < nkt; kt++) {
            CP_WAIT1();
            __syncthreads();
            if (kt + 2 < nkt) { issue((kt + 2) % NSTG, kt + 2); }
            CP_COMMIT();

            int s = kt % NSTG;
            uint32_t aS = smemu + s * STG;
            uint32_t bS = aS + STG_M;
            #pragma unroll
            for (int kk = 0; kk < 4; kk++) {
                uint32_t rb[4][2];
                #pragma unroll
                for (int nt = 0; nt < 4; nt++)
                    LDSM_X2(rb[nt], bS + bRowOff + nt * 8 * SROW + kk * 32);
                #pragma unroll
                for (int mt = 0; mt < 4; mt++) {
                    uint32_t ra[4];
                    LDSM_X4(ra, aS + aRowOff + mt * 16 * SROW + kk * 32);
                    #pragma unroll
                    for (int nt = 0; nt < 4; nt++)
                        MMA16816(acc[mt][nt], ra, rb[nt]);
                }
            }
        }
        CP_WAIT0();
        __syncthreads();

        // --- epilogue (permuted space; masks from real targets) -------------
        float sqi[8], sqj[8];
        int   ti[8], tj[8];
        #pragma unroll
        for (int mt = 0; mt < 4; mt++)
            #pragma unroll
            for (int h = 0; h < 2; h++) {
                int gi = min(iBase + mWarp + mt * 16 + (lane >> 2) + h * 8, n - 1);
                sqi[mt * 2 + h] = g_sq[gi];
                ti[mt * 2 + h]  = g_tgtp[gi];
            }
        #pragma unroll
        for (int nt = 0; nt < 4; nt++)
            #pragma unroll
            for (int pp = 0; pp < 2; pp++) {
                int gj = min(jBase + nWarp + nt * 8 + 2 * (lane & 3) + pp, n - 1);
                sqj[nt * 2 + pp] = g_sq[gj];
                tj[nt * 2 + pp]  = g_tgtp[gj];
            }

        unsigned rmax[8], rmin[8], cmax[8], cmin[8];
        #pragma unroll
        for (int q = 0; q < 8; q++) { rmax[q] = 0u; rmin[q] = UINF; cmax[q] = 0u; cmin[q] = UINF; }

        #pragma unroll
        for (int mt = 0; mt < 4; mt++)
            #pragma unroll
            for (int nt = 0; nt < 4; nt++)
                #pragma unroll
                for (int e = 0; e < 4; e++) {
                    int h = e >> 1, pp = e & 1;
                    int ri = mt * 2 + h, cj = nt * 2 + pp;
                    float d2 = fmaxf(sqi[ri] + sqj[cj] - 2.f * acc[mt][nt][(h << 1) | pp], 1e-12f);
                    unsigned b = __float_as_uint(d2);
                    bool same = (ti[ri] == tj[cj]);
                    bool zn   = !same && (ti[ri] == 0 || tj[cj] == 0);
                    if (same) { rmax[ri] = max(rmax[ri], b); cmax[cj] = max(cmax[cj], b); }
                    if (zn)   { rmin[ri] = min(rmin[ri], b); cmin[cj] = min(cmin[cj], b); }
                }

        unsigned* sredmax = (unsigned*)(smem + SM_RED);
        unsigned* sredmin = sredmax + 256;
        sredmax[tid] = 0u;
        sredmin[tid] = UINF;
        __syncthreads();

        #pragma unroll
        for (int mt = 0; mt < 4; mt++)
            #pragma unroll
            for (int h = 0; h < 2; h++) {
                int q = mt * 2 + h;
                int loc = mWarp + mt * 16 + (lane >> 2) + h * 8;
                if (rmax[q]) atomicMax(&sredmax[loc], rmax[q]);
                if (rmin[q] != UINF) atomicMin(&sredmin[loc], rmin[q]);
            }
        #pragma unroll
        for (int nt = 0; nt < 4; nt++)
            #pragma unroll
            for (int pp = 0; pp < 2; pp++) {
                int q = nt * 2 + pp;
                int loc = 128 + nWarp + nt * 8 + 2 * (lane & 3) + pp;
                if (cmax[q]) atomicMax(&sredmax[loc], cmax[q]);
                if (cmin[q] != UINF) atomicMin(&sredmin[loc], cmin[q]);
            }
        __syncthreads();

        {
            int row = (tid < 128) ? min(iBase + tid, n - 1) : min(jBase + (tid - 128), n - 1);
            if (sredmax[tid]) atomicMax(&g_max2[row], sredmax[tid]);
            if (sredmin[tid] != UINF) atomicMin(&g_min2[row], sredmin[tid]);
        }
        __syncthreads();
    }

    // --- last-CTA tail: full loss reduction ----------------------------------
    __threadfence();
    __shared__ int amlast;
    if (tid == 0) amlast = (atomicAdd(&g_done, 1) == (int)gridDim.x - 1);
    __syncthreads();
    if (amlast) {
        int flag = g_flag;
        float s = 0.f;
        for (int i = tid; i < n; i += 256) {
            float ap = sqrtf(__uint_as_float(__ldcg(&g_max2[i])));
            float an = flag ? sqrtf(__uint_as_float(__ldcg(&g_min2[i]))) : 0.f;
            s += fmaxf(ap - an + MARGIN, 0.f);   // min2==+inf & flag -> -inf -> 0
        }
        float* ssum = (float*)(smem + SM_RED);
        ssum[tid] = s;
        __syncthreads();
        #pragma unroll
        for (int o = 128; o; o >>= 1) {
            if (tid < o) ssum[tid] += ssum[tid + o];
            __syncthreads();
        }
        if (tid == 0) out[0] = ssum[0] / (float)n;
    }
}

// ======================= legacy fp32 fallback (proven, R2) ==================
__global__ void legacy_prep(const float* __restrict__ x, const int* __restrict__ tgt,
                            int n, int d) {
    int warp = (blockIdx.x * blockDim.x + threadIdx.x) >> 5;
    int lane = threadIdx.x & 31;
    if (warp < n) {
        const float4* row = (const float4*)(x + (size_t)warp * d);
        int nv = d >> 2;
        float s = 0.f;
        for (int v = lane; v < nv; v += 32) {
            float4 f = row[v];
            s += f.x * f.x + f.y * f.y + f.z * f.z + f.w * f.w;
        }
        #pragma unroll
        for (int o = 16; o; o >>= 1) s += __shfl_xor_sync(0xffffffffu, s, o);
        if (lane == 0) {
            g_sq[warp]   = s;
            g_max2[warp] = 0u;
            g_min2[warp] = 0x7f800000u;
        }
    }
    if (blockIdx.x == 0) {
        int t0 = tgt[0];
        int loc = 0;
        for (int j = threadIdx.x; j < n; j += blockDim.x) {
            int tj = tgt[j];
            if ((t0 != tj) && (t0 == 0 || tj == 0)) loc = 1;
        }
        int f = __syncthreads_or(loc);
        if (threadIdx.x == 0) g_flag = f;
    }
}

#define LT    128
#define LKT   16
#define LPAD  4
__global__ void __launch_bounds__(256, 2)
gemm_reduce_legacy(const float* __restrict__ x, const int* __restrict__ tgt,
                   int n, int d, int nb) {
    int p = blockIdx.x, bi = 0, rem = p;
    while (rem >= nb - bi) { rem -= (nb - bi); bi++; }
    int bj = bi + rem;
    const int iBase = bi * LT;
    const int jBase = bj * LT;
    const int tid = threadIdx.x;
    const int tx = tid & 15;
    const int ty = tid >> 4;

    __shared__ float As[LKT][LT + LPAD];
    __shared__ float Bs[LKT][LT + LPAD];
    __shared__ unsigned sredmax[2 * LT];
    __shared__ unsigned sredmin[2 * LT];

    float acc[8][8];
    #pragma unroll
    for (int r = 0; r < 8; r++)
        #pragma unroll
        for (int c = 0; c < 8; c++) acc[r][c] = 0.f;

    const int nkt = d / LKT;
    float4 pa[2], pb[2];
    #pragma unroll
    for (int u = 0; u < 2; u++) {
        int idx = tid + u * 256, r = idx >> 2, c4 = idx & 3;
        pa[u] = *(const float4*)(x + (size_t)(iBase + r) * d + c4 * 4);
        pb[u] = *(const float4*)(x + (size_t)(jBase + r) * d + c4 * 4);
    }
    #pragma unroll
    for (int u = 0; u < 2; u++) {
        int idx = tid + u * 256, r = idx >> 2, c4 = idx & 3;
        As[c4*4+0][r]=pa[u].x; As[c4*4+1][r]=pa[u].y; As[c4*4+2][r]=pa[u].z; As[c4*4+3][r]=pa[u].w;
        Bs[c4*4+0][r]=pb[u].x; Bs[c4*4+1][r]=pb[u].y; Bs[c4*4+2][r]=pb[u].z; Bs[c4*4+3][r]=pb[u].w;
    }
    __syncthreads();
    for (int kt = 0; kt < nkt; kt++) {
        if (kt + 1 < nkt) {
            int k0 = (kt + 1) * LKT;
            #pragma unroll
            for (int u = 0; u < 2; u++) {
                int idx = tid + u * 256, r = idx >> 2, c4 = idx & 3;
                pa[u] = *(const float4*)(x + (size_t)(iBase + r) * d + k0 + c4 * 4);
                pb[u] = *(const float4*)(x + (size_t)(jBase + r) * d + k0 + c4 * 4);
            }
        }
        #pragma unroll
        for (int k = 0; k < LKT; k++) {
            float a[8], b[8];
            *(float4*)(a)   = *(const float4*)&As[k][ty*8];
            *(float4*)(a+4) = *(const float4*)&As[k][ty*8+4];
            *(float4*)(b)   = *(const float4*)&Bs[k][tx*8];
            *(float4*)(b+4) = *(const float4*)&Bs[k][tx*8+4];
            #pragma unroll
            for (int r = 0; r < 8; r++)
                #pragma unroll
                for (int c = 0; c < 8; c++) acc[r][c] += a[r] * b[c];
        }
        __syncthreads();
        if (kt + 1 < nkt) {
            #pragma unroll
            for (int u = 0; u < 2; u++) {
                int idx = tid + u * 256, r = idx >> 2, c4 = idx & 3;
                As[c4*4+0][r]=pa[u].x; As[c4*4+1][r]=pa[u].y; As[c4*4+2][r]=pa[u].z; As[c4*4+3][r]=pa[u].w;
                Bs[c4*4+0][r]=pb[u].x; Bs[c4*4+1][r]=pb[u].y; Bs[c4*4+2][r]=pb[u].z; Bs[c4*4+3][r]=pb[u].w;
            }
            __syncthreads();
        }
    }

    float sqi[8], sqj[8];
    int ti8[8], tj8[8];
    #pragma unroll
    for (int r = 0; r < 8; r++) { int i = iBase + ty*8 + r; sqi[r] = g_sq[i]; ti8[r] = tgt[i]; }
    #pragma unroll
    for (int c = 0; c < 8; c++) { int j = jBase + tx*8 + c; sqj[c] = g_sq[j]; tj8[c] = tgt[j]; }

    const float INF = __uint_as_float(0x7f800000u);
    float rmax[8], rmin[8], cmax[8], cmin[8];
    #pragma unroll
    for (int r = 0; r < 8; r++) { rmax[r] = 0.f; rmin[r] = INF; }
    #pragma unroll
    for (int c = 0; c < 8; c++) { cmax[c] = 0.f; cmin[c] = INF; }
    #pragma unroll
    for (int r = 0; r < 8; r++)
        #pragma unroll
        for (int c = 0; c < 8; c++) {
            float d2 = fmaxf(sqi[r] + sqj[c] - 2.f * acc[r][c], 1e-12f);
            bool same = (ti8[r] == tj8[c]);
            bool zn = !same && (ti8[r] == 0 || tj8[c] == 0);
            if (same) { rmax[r] = fmaxf(rmax[r], d2); cmax[c] = fmaxf(cmax[c], d2); }
            if (zn)   { rmin[r] = fminf(rmin[r], d2); cmin[c] = fminf(cmin[c], d2); }
        }
    sredmax[tid] = 0u; sredmin[tid] = 0x7f800000u;
    __syncthreads();
    #pragma unroll
    for (int r = 0; r < 8; r++) {
        atomicMax(&sredmax[ty*8+r], __float_as_uint(rmax[r]));
        atomicMin(&sredmin[ty*8+r], __float_as_uint(rmin[r]));
    }
    #pragma unroll
    for (int c = 0; c < 8; c++) {
        atomicMax(&sredmax[LT + tx*8+c], __float_as_uint(cmax[c]));
        atomicMin(&sredmin[LT + tx*8+c], __float_as_uint(cmin[c]));
    }
    __syncthreads();
    int row = (tid < LT) ? (iBase + tid) : (jBase + (tid - LT));
    atomicMax(&g_max2[row], sredmax[tid]);
    atomicMin(&g_min2[row], sredmin[tid]);
}

__global__ void partial_kernel(int n) {
    __shared__ float ssum[256];
    int flag = g_flag;
    int chunk = (n + NPART - 1) / NPART;
    int beg = blockIdx.x * chunk;
    int end = min(beg + chunk, n);
    float s = 0.f;
    for (int i = beg + (int)threadIdx.x; i < end; i += blockDim.x) {
        float ap = sqrtf(__uint_as_float(g_max2[i]));
        float an = flag ? sqrtf(__uint_as_float(g_min2[i])) : 0.f;
        s += fmaxf(ap - an + MARGIN, 0.f);
    }
    ssum[threadIdx.x] = s;
    __syncthreads();
    #pragma unroll
    for (int o = 128; o; o >>= 1) {
        if (threadIdx.x < o) ssum[threadIdx.x] += ssum[threadIdx.x + o];
        __syncthreads();
    }
    if (threadIdx.x == 0) g_partial[blockIdx.x] = ssum[0];
}

__global__ void final_kernel(float* __restrict__ out, int n) {
    if (threadIdx.x == 0) {
        float s = 0.f;
        #pragma unroll
        for (int b = 0; b < NPART; b++) s += g_partial[b];
        out[0] = s / (float)n;
    }
}

// ======================= host launcher ======================================
extern "C" void kernel_launch(void* const* d_in, const int* in_sizes, int n_in,
                              void* d_out, int out_size) {
    const float* x   = (const float*)d_in[0];
    const int*   tgt = (const int*)d_in[1];   // int32 (JAX x64 disabled)
    int n = in_sizes[1];
    int d = in_sizes[0] / n;

    bool tc_ok = (n % 128 == 0) && (d % BKE == 0) && (d / BKE >= 2) &&
                 (n <= N_MAX) && ((size_t)n * d <= (size_t)N_MAX * D_MAX);
    if (tc_ok) {
        static bool attr_set = false;
        if (!attr_set) {
            cudaFuncSetAttribute(gemm_mma_kernel,
                                 cudaFuncAttributeMaxDynamicSharedMemorySize, SM_TOTAL);
            attr_set = true;
        }
        sort_kernel<<<1, 1024>>>(tgt, n);
        prep_kernel<<<(n + 7) / 8, 256>>>(x, n, d);
        gemm_mma_kernel<<<296, 256, SM_TOTAL>>>((float*)d_out, n, d);
    } else {
        legacy_prep<<<(n + 7) / 8, 256>>>(x, tgt, n, d);
        int nb = n / LT;
        int nblocks = nb * (nb + 1) / 2;
        gemm_reduce_legacy<<<nblocks, 256>>>(x, tgt, n, d, nb);
        partial_kernel<<<NPART, 256>>>(n);
        final_kernel<<<1, 32>>>((float*)d_out, n);
    }
}

// round 15
// speedup vs baseline: 4.0024x; 1.1992x over previous
#include <cuda_runtime.h>
#include <cuda_bf16.h>
#include <cstdint>

#define N_MAX   4096
#define D_MAX   2048
#define NCLS    32
#define MARGIN  0.3f
#define NPART   16

__device__ float           g_sq[N_MAX];      // SOURCE-space row sumsq
__device__ unsigned        g_max2[N_MAX];    // position-space reductions
__device__ unsigned        g_min2[N_MAX];
__device__ int             g_flag;
__device__ int             g_done;
__device__ int             g_perm[N_MAX];    // position -> source row
__device__ int             g_tgtp[N_MAX];    // position -> target (sorted)
__device__ int2            g_tiles[4608];
__device__ int             g_ntiles;
__device__ float           g_partial[NPART];
__device__ __nv_bfloat16   g_xb[(size_t)N_MAX * D_MAX];  // SOURCE-order bf16 rows

// ======= prep: block 0 sorts + builds tile table; other blocks convert ======
__global__ void prep_kernel(const float* __restrict__ x, const int* __restrict__ tgt,
                            int n, int d) {
    if (blockIdx.x == 0) {
        // ---- sort block: histogram + scatter + flag + tile table ----
        __shared__ int scnt[NCLS], soff[NCLS], sfill[NCLS];
        int tid = threadIdx.x;
        if (tid < NCLS) scnt[tid] = 0;
        __syncthreads();
        for (int i = tid; i < n; i += blockDim.x) atomicAdd(&scnt[tgt[i]], 1);
        __syncthreads();
        if (tid == 0) {
            int acc = 0;
            for (int c = 0; c < NCLS; c++) { soff[c] = acc; sfill[c] = acc; acc += scnt[c]; }
        }
        __syncthreads();
        for (int i = tid; i < n; i += blockDim.x) {
            int c = tgt[i];
            int pos = atomicAdd(&sfill[c], 1);
            g_perm[pos] = i;
            g_tgtp[pos] = c;
        }
        if (tid == 0) {
            int t0 = tgt[0];
            int c0 = scnt[0];
            g_flag = (t0 == 0) ? ((n - c0) > 0 ? 1 : 0) : (c0 > 0 ? 1 : 0);
            g_done = 0;
            // tiles: 128 rows x 64 cols
            int nt = 0;
            int nb64 = (n + 63) >> 6;
            for (int c = 0; c < NCLS; c++) {
                int off = soff[c], cnt = scnt[c];
                int t128 = (cnt + 127) >> 7;
                int t64  = (cnt + 63) >> 6;
                for (int a = 0; a < t128; a++)
                    for (int b = 0; b < t64; b++)
                        if (b * 64 + 64 > a * 128)            // triangular prune
                            g_tiles[nt++] = make_int2(off + a * 128, off + b * 64);
            }
            int ti0 = (c0 + 127) >> 7;                        // class-0 row tiles
            for (int a = 0; a < ti0; a++)
                for (int jb = (c0 >> 6); jb < nb64; jb++)
                    g_tiles[nt++] = make_int2(a * 128, jb * 64);
            g_ntiles = nt;
        }
        return;
    }

    // ---- convert blocks: source-order norms + bf16 (8 rows per block) ----
    int row = (blockIdx.x - 1) * 8 + (threadIdx.x >> 5);
    int lane = threadIdx.x & 31;
    if (row >= n) return;
    const float4* src = (const float4*)(x + (size_t)row * d);
    uint4* orow = (uint4*)(g_xb + (size_t)row * d);
    int nv = d >> 3;
    float s = 0.f;
    for (int v = lane; v < nv; v += 32) {
        float4 f0 = src[v * 2];
        float4 f1 = src[v * 2 + 1];
        s += f0.x * f0.x + f0.y * f0.y + f0.z * f0.z + f0.w * f0.w;
        s += f1.x * f1.x + f1.y * f1.y + f1.z * f1.z + f1.w * f1.w;
        __nv_bfloat162 h0 = __floats2bfloat162_rn(f0.x, f0.y);
        __nv_bfloat162 h1 = __floats2bfloat162_rn(f0.z, f0.w);
        __nv_bfloat162 h2 = __floats2bfloat162_rn(f1.x, f1.y);
        __nv_bfloat162 h3 = __floats2bfloat162_rn(f1.z, f1.w);
        uint4 o;
        o.x = *(uint32_t*)&h0; o.y = *(uint32_t*)&h1;
        o.z = *(uint32_t*)&h2; o.w = *(uint32_t*)&h3;
        orow[v] = o;
    }
    #pragma unroll
    for (int o = 16; o; o >>= 1) s += __shfl_xor_sync(0xffffffffu, s, o);
    if (lane == 0) {
        g_sq[row]   = s;
        g_max2[row] = 0u;          // position-space init (full coverage: 0..n-1)
        g_min2[row] = 0x7f800000u;
    }
}

// ======================= PTX helpers (baseline ISA only) ====================
__device__ __forceinline__ uint32_t smem_u32(const void* p) {
    uint32_t a;
    asm("{ .reg .u64 t; cvta.to.shared.u64 t, %1; cvt.u32.u64 %0, t; }" : "=r"(a) : "l"(p));
    return a;
}
#define CP16(sa, ga) \
    asm volatile("cp.async.cg.shared.global [%0], [%1], 16;" :: "r"(sa), "l"(ga) : "memory")
#define CP_COMMIT()  asm volatile("cp.async.commit_group;" ::: "memory")
#define CP_WAIT1()   asm volatile("cp.async.wait_group 1;" ::: "memory")
#define CP_WAIT0()   asm volatile("cp.async.wait_group 0;" ::: "memory")

#define LDSM_X4(r, a) \
    asm volatile("ldmatrix.sync.aligned.m8n8.x4.shared.b16 {%0,%1,%2,%3}, [%4];" \
        : "=r"((r)[0]), "=r"((r)[1]), "=r"((r)[2]), "=r"((r)[3]) : "r"(a))
#define LDSM_X2(r, a) \
    asm volatile("ldmatrix.sync.aligned.m8n8.x2.shared.b16 {%0,%1}, [%2];" \
        : "=r"((r)[0]), "=r"((r)[1]) : "r"(a))

#define MMA16816(c, a, b) \
    asm volatile("mma.sync.aligned.m16n8k16.row.col.f32.bf16.bf16.f32 " \
        "{%0,%1,%2,%3},{%4,%5,%6,%7},{%8,%9},{%0,%1,%2,%3};" \
        : "+f"((c)[0]), "+f"((c)[1]), "+f"((c)[2]), "+f"((c)[3]) \
        : "r"((a)[0]), "r"((a)[1]), "r"((a)[2]), "r"((a)[3]), "r"((b)[0]), "r"((b)[1]))

// ========== sparse-tile bf16 GEMM (128x64 tiles) + reductions + loss ========
#define BM    128
#define BN    64
#define BKE   64                 // bf16 elems per K stage (128 B rows)
#define SROW  144
#define STG_A (BM * SROW)        // 18432
#define STG_B (BN * SROW)        // 9216
#define STG   (STG_A + STG_B)    // 27648
#define NSTG  3
#define SM_RED   (NSTG * STG)              // 82944
#define SM_TOTAL (SM_RED + 2048)           // 84992

__global__ void __launch_bounds__(256, 2)
gemm_mma_kernel(float* __restrict__ out, int n, int d) {
    extern __shared__ char smem[];
    const uint32_t smemu = smem_u32(smem);
    const int tid  = threadIdx.x;
    const int wid  = tid >> 5;
    const int lane = tid & 31;
    const int nkt  = d / BKE;
    const size_t dB = (size_t)d * 2;

    const int mWarp = (wid >> 2) * 64;         // 2 warps in M
    const int nWarp = (wid & 3) * 16;          // 4 warps in N, 16 cols each
    const uint32_t aRowOff = (mWarp + (lane & 15)) * SROW + ((lane >> 4) & 1) * 16;
    const uint32_t bRowOff = (nWarp + (lane & 7))  * SROW + ((lane >> 3) & 1) * 16;
    const unsigned UINF = 0x7f800000u;

    int ntiles = g_ntiles;
    for (int tix = blockIdx.x; tix < ntiles; tix += gridDim.x) {
        int2 tile = g_tiles[tix];
        const int iBase = tile.x;
        const int jBase = tile.y;

        // cache gather indices for this tile (cp.async tasks fixed per thread)
        const char* srcA[4];
        const char* srcB[2];
        #pragma unroll
        for (int t = 0; t < 4; t++) {
            int r = (tid + t * 256) >> 3;
            srcA[t] = (const char*)g_xb + (size_t)g_perm[min(iBase + r, n - 1)] * dB;
        }
        #pragma unroll
        for (int t = 0; t < 2; t++) {
            int r = (tid + t * 256) >> 3;
            srcB[t] = (const char*)g_xb + (size_t)g_perm[min(jBase + r, n - 1)] * dB;
        }

        float acc[4][2][4];
        #pragma unroll
        for (int mt = 0; mt < 4; mt++)
            #pragma unroll
            for (int nt = 0; nt < 2; nt++)
                #pragma unroll
                for (int e = 0; e < 4; e++) acc[mt][nt][e] = 0.f;

        auto issue = [&](int s, int kt) {
            uint32_t aS = smemu + s * STG;
            uint32_t bS = aS + STG_A;
            int koff = kt * 128;
            #pragma unroll
            for (int t = 0; t < 4; t++) {
                int chunk = tid + t * 256;
                uint32_t so = (chunk >> 3) * SROW + (chunk & 7) * 16;
                CP16(aS + so, srcA[t] + koff + (chunk & 7) * 16);
            }
            #pragma unroll
            for (int t = 0; t < 2; t++) {
                int chunk = tid + t * 256;
                uint32_t so = (chunk >> 3) * SROW + (chunk & 7) * 16;
                CP16(bS + so, srcB[t] + koff + (chunk & 7) * 16);
            }
        };

        issue(0, 0); CP_COMMIT();
        issue(1, 1); CP_COMMIT();

        for (int kt = 0; kt < nkt; kt++) {
            CP_WAIT1();
            __syncthreads();
            if (kt + 2 < nkt) { issue((kt + 2) % NSTG, kt + 2); }
            CP_COMMIT();

            int s = kt % NSTG;
            uint32_t aS = smemu + s * STG;
            uint32_t bS = aS + STG_A;
            #pragma unroll
            for (int kk = 0; kk < 4; kk++) {
                uint32_t rb[2][2];
                #pragma unroll
                for (int nt = 0; nt < 2; nt++)
                    LDSM_X2(rb[nt], bS + bRowOff + nt * 8 * SROW + kk * 32);
                #pragma unroll
                for (int mt = 0; mt < 4; mt++) {
                    uint32_t ra[4];
                    LDSM_X4(ra, aS + aRowOff + mt * 16 * SROW + kk * 32);
                    #pragma unroll
                    for (int nt = 0; nt < 2; nt++)
                        MMA16816(acc[mt][nt], ra, rb[nt]);
                }
            }
        }
        CP_WAIT0();
        __syncthreads();

        // --- epilogue (position space; data via perm) ------------------------
        float sqi[8], sqj[4];
        int   ti[8], tj[4];
        #pragma unroll
        for (int mt = 0; mt < 4; mt++)
            #pragma unroll
            for (int h = 0; h < 2; h++) {
                int pos = min(iBase + mWarp + mt * 16 + (lane >> 2) + h * 8, n - 1);
                sqi[mt * 2 + h] = g_sq[g_perm[pos]];
                ti[mt * 2 + h]  = g_tgtp[pos];
            }
        #pragma unroll
        for (int nt = 0; nt < 2; nt++)
            #pragma unroll
            for (int pp = 0; pp < 2; pp++) {
                int pos = min(jBase + nWarp + nt * 8 + 2 * (lane & 3) + pp, n - 1);
                sqj[nt * 2 + pp] = g_sq[g_perm[pos]];
                tj[nt * 2 + pp]  = g_tgtp[pos];
            }

        unsigned rmax[8], rmin[8], cmax[4], cmin[4];
        #pragma unroll
        for (int q = 0; q < 8; q++) { rmax[q] = 0u; rmin[q] = UINF; }
        #pragma unroll
        for (int q = 0; q < 4; q++) { cmax[q] = 0u; cmin[q] = UINF; }

        #pragma unroll
        for (int mt = 0; mt < 4; mt++)
            #pragma unroll
            for (int nt = 0; nt < 2; nt++)
                #pragma unroll
                for (int e = 0; e < 4; e++) {
                    int h = e >> 1, pp = e & 1;
                    int ri = mt * 2 + h, cj = nt * 2 + pp;
                    float d2 = fmaxf(sqi[ri] + sqj[cj] - 2.f * acc[mt][nt][(h << 1) | pp], 1e-12f);
                    unsigned b = __float_as_uint(d2);
                    bool same = (ti[ri] == tj[cj]);
                    bool zn   = !same && (ti[ri] == 0 || tj[cj] == 0);
                    if (same) { rmax[ri] = max(rmax[ri], b); cmax[cj] = max(cmax[cj], b); }
                    if (zn)   { rmin[ri] = min(rmin[ri], b); cmin[cj] = min(cmin[cj], b); }
                }

        unsigned* sredmax = (unsigned*)(smem + SM_RED);   // 192 slots
        unsigned* sredmin = sredmax + 192;
        if (tid < 192) { sredmax[tid] = 0u; sredmin[tid] = UINF; }
        __syncthreads();

        #pragma unroll
        for (int mt = 0; mt < 4; mt++)
            #pragma unroll
            for (int h = 0; h < 2; h++) {
                int q = mt * 2 + h;
                int loc = mWarp + mt * 16 + (lane >> 2) + h * 8;
                if (rmax[q]) atomicMax(&sredmax[loc], rmax[q]);
                if (rmin[q] != UINF) atomicMin(&sredmin[loc], rmin[q]);
            }
        #pragma unroll
        for (int nt = 0; nt < 2; nt++)
            #pragma unroll
            for (int pp = 0; pp < 2; pp++) {
                int q = nt * 2 + pp;
                int loc = 128 + nWarp + nt * 8 + 2 * (lane & 3) + pp;
                if (cmax[q]) atomicMax(&sredmax[loc], cmax[q]);
                if (cmin[q] != UINF) atomicMin(&sredmin[loc], cmin[q]);
            }
        __syncthreads();

        if (tid < 192) {
            int pos = (tid < 128) ? min(iBase + tid, n - 1) : min(jBase + (tid - 128), n - 1);
            if (sredmax[tid]) atomicMax(&g_max2[pos], sredmax[tid]);
            if (sredmin[tid] != UINF) atomicMin(&g_min2[pos], sredmin[tid]);
        }
        __syncthreads();
    }

    // --- last-CTA tail: full loss reduction ----------------------------------
    __threadfence();
    __shared__ int amlast;
    if (tid == 0) amlast = (atomicAdd(&g_done, 1) == (int)gridDim.x - 1);
    __syncthreads();
    if (amlast) {
        int flag = g_flag;
        float s = 0.f;
        for (int i = tid; i < n; i += 256) {
            float ap = sqrtf(__uint_as_float(__ldcg(&g_max2[i])));
            float an = flag ? sqrtf(__uint_as_float(__ldcg(&g_min2[i]))) : 0.f;
            s += fmaxf(ap - an + MARGIN, 0.f);   // min2==+inf & flag -> -inf -> 0
        }
        float* ssum = (float*)(smem + SM_RED);
        ssum[tid] = s;
        __syncthreads();
        #pragma unroll
        for (int o = 128; o; o >>= 1) {
            if (tid < o) ssum[tid] += ssum[tid + o];
            __syncthreads();
        }
        if (tid == 0) out[0] = ssum[0] / (float)n;
    }
}

// ======================= legacy fp32 fallback (proven, R2) ==================
__global__ void legacy_prep(const float* __restrict__ x, const int* __restrict__ tgt,
                            int n, int d) {
    int warp = (blockIdx.x * blockDim.x + threadIdx.x) >> 5;
    int lane = threadIdx.x & 31;
    if (warp < n) {
        const float4* row = (const float4*)(x + (size_t)warp * d);
        int nv = d >> 2;
        float s = 0.f;
        for (int v = lane; v < nv; v += 32) {
            float4 f = row[v];
            s += f.x * f.x + f.y * f.y + f.z * f.z + f.w * f.w;
        }
        #pragma unroll
        for (int o = 16; o; o >>= 1) s += __shfl_xor_sync(0xffffffffu, s, o);
        if (lane == 0) {
            g_sq[warp]   = s;
            g_max2[warp] = 0u;
            g_min2[warp] = 0x7f800000u;
        }
    }
    if (blockIdx.x == 0) {
        int t0 = tgt[0];
        int loc = 0;
        for (int j = threadIdx.x; j < n; j += blockDim.x) {
            int tj = tgt[j];
            if ((t0 != tj) && (t0 == 0 || tj == 0)) loc = 1;
        }
        int f = __syncthreads_or(loc);
        if (threadIdx.x == 0) g_flag = f;
    }
}

#define LT    128
#define LKT   16
#define LPAD  4
__global__ void __launch_bounds__(256, 2)
gemm_reduce_legacy(const float* __restrict__ x, const int* __restrict__ tgt,
                   int n, int d, int nb) {
    int p = blockIdx.x, bi = 0, rem = p;
    while (rem >= nb - bi) { rem -= (nb - bi); bi++; }
    int bj = bi + rem;
    const int iBase = bi * LT;
    const int jBase = bj * LT;
    const int tid = threadIdx.x;
    const int tx = tid & 15;
    const int ty = tid >> 4;

    __shared__ float As[LKT][LT + LPAD];
    __shared__ float Bs[LKT][LT + LPAD];
    __shared__ unsigned sredmax[2 * LT];
    __shared__ unsigned sredmin[2 * LT];

    float acc[8][8];
    #pragma unroll
    for (int r = 0; r < 8; r++)
        #pragma unroll
        for (int c = 0; c < 8; c++) acc[r][c] = 0.f;

    const int nkt = d / LKT;
    float4 pa[2], pb[2];
    #pragma unroll
    for (int u = 0; u < 2; u++) {
        int idx = tid + u * 256, r = idx >> 2, c4 = idx & 3;
        pa[u] = *(const float4*)(x + (size_t)(iBase + r) * d + c4 * 4);
        pb[u] = *(const float4*)(x + (size_t)(jBase + r) * d + c4 * 4);
    }
    #pragma unroll
    for (int u = 0; u < 2; u++) {
        int idx = tid + u * 256, r = idx >> 2, c4 = idx & 3;
        As[c4*4+0][r]=pa[u].x; As[c4*4+1][r]=pa[u].y; As[c4*4+2][r]=pa[u].z; As[c4*4+3][r]=pa[u].w;
        Bs[c4*4+0][r]=pb[u].x; Bs[c4*4+1][r]=pb[u].y; Bs[c4*4+2][r]=pb[u].z; Bs[c4*4+3][r]=pb[u].w;
    }
    __syncthreads();
    for (int kt = 0; kt < nkt; kt++) {
        if (kt + 1 < nkt) {
            int k0 = (kt + 1) * LKT;
            #pragma unroll
            for (int u = 0; u < 2; u++) {
                int idx = tid + u * 256, r = idx >> 2, c4 = idx & 3;
                pa[u] = *(const float4*)(x + (size_t)(iBase + r) * d + k0 + c4 * 4);
                pb[u] = *(const float4*)(x + (size_t)(jBase + r) * d + k0 + c4 * 4);
            }
        }
        #pragma unroll
        for (int k = 0; k < LKT; k++) {
            float a[8], b[8];
            *(float4*)(a)   = *(const float4*)&As[k][ty*8];
            *(float4*)(a+4) = *(const float4*)&As[k][ty*8+4];
            *(float4*)(b)   = *(const float4*)&Bs[k][tx*8];
            *(float4*)(b+4) = *(const float4*)&Bs[k][tx*8+4];
            #pragma unroll
            for (int r = 0; r < 8; r++)
                #pragma unroll
                for (int c = 0; c < 8; c++) acc[r][c] += a[r] * b[c];
        }
        __syncthreads();
        if (kt + 1 < nkt) {
            #pragma unroll
            for (int u = 0; u < 2; u++) {
                int idx = tid + u * 256, r = idx >> 2, c4 = idx & 3;
                As[c4*4+0][r]=pa[u].x; As[c4*4+1][r]=pa[u].y; As[c4*4+2][r]=pa[u].z; As[c4*4+3][r]=pa[u].w;
                Bs[c4*4+0][r]=pb[u].x; Bs[c4*4+1][r]=pb[u].y; Bs[c4*4+2][r]=pb[u].z; Bs[c4*4+3][r]=pb[u].w;
            }
            __syncthreads();
        }
    }

    float sqi[8], sqj[8];
    int ti8[8], tj8[8];
    #pragma unroll
    for (int r = 0; r < 8; r++) { int i = iBase + ty*8 + r; sqi[r] = g_sq[i]; ti8[r] = tgt[i]; }
    #pragma unroll
    for (int c = 0; c < 8; c++) { int j = jBase + tx*8 + c; sqj[c] = g_sq[j]; tj8[c] = tgt[j]; }

    const float INF = __uint_as_float(0x7f800000u);
    float rmax[8], rmin[8], cmax[8], cmin[8];
    #pragma unroll
    for (int r = 0; r < 8; r++) { rmax[r] = 0.f; rmin[r] = INF; }
    #pragma unroll
    for (int c = 0; c < 8; c++) { cmax[c] = 0.f; cmin[c] = INF; }
    #pragma unroll
    for (int r = 0; r < 8; r++)
        #pragma unroll
        for (int c = 0; c < 8; c++) {
            float d2 = fmaxf(sqi[r] + sqj[c] - 2.f * acc[r][c], 1e-12f);
            bool same = (ti8[r] == tj8[c]);
            bool zn = !same && (ti8[r] == 0 || tj8[c] == 0);
            if (same) { rmax[r] = fmaxf(rmax[r], d2); cmax[c] = fmaxf(cmax[c], d2); }
            if (zn)   { rmin[r] = fminf(rmin[r], d2); cmin[c] = fminf(cmin[c], d2); }
        }
    sredmax[tid] = 0u; sredmin[tid] = 0x7f800000u;
    __syncthreads();
    #pragma unroll
    for (int r = 0; r < 8; r++) {
        atomicMax(&sredmax[ty*8+r], __float_as_uint(rmax[r]));
        atomicMin(&sredmin[ty*8+r], __float_as_uint(rmin[r]));
    }
    #pragma unroll
    for (int c = 0; c < 8; c++) {
        atomicMax(&sredmax[LT + tx*8+c], __float_as_uint(cmax[c]));
        atomicMin(&sredmin[LT + tx*8+c], __float_as_uint(cmin[c]));
    }
    __syncthreads();
    int row = (tid < LT) ? (iBase + tid) : (jBase + (tid - LT));
    atomicMax(&g_max2[row], sredmax[tid]);
    atomicMin(&g_min2[row], sredmin[tid]);
}

__global__ void partial_kernel(int n) {
    __shared__ float ssum[256];
    int flag = g_flag;
    int chunk = (n + NPART - 1) / NPART;
    int beg = blockIdx.x * chunk;
    int end = min(beg + chunk, n);
    float s = 0.f;
    for (int i = beg + (int)threadIdx.x; i < end; i += blockDim.x) {
        float ap = sqrtf(__uint_as_float(g_max2[i]));
        float an = flag ? sqrtf(__uint_as_float(g_min2[i])) : 0.f;
        s += fmaxf(ap - an + MARGIN, 0.f);
    }
    ssum[threadIdx.x] = s;
    __syncthreads();
    #pragma unroll
    for (int o = 128; o; o >>= 1) {
        if (threadIdx.x < o) ssum[threadIdx.x] += ssum[threadIdx.x + o];
        __syncthreads();
    }
    if (threadIdx.x == 0) g_partial[blockIdx.x] = ssum[0];
}

__global__ void final_kernel(float* __restrict__ out, int n) {
    if (threadIdx.x == 0) {
        float s = 0.f;
        #pragma unroll
        for (int b = 0; b < NPART; b++) s += g_partial[b];
        out[0] = s / (float)n;
    }
}

// ======================= host launcher ======================================
extern "C" void kernel_launch(void* const* d_in, const int* in_sizes, int n_in,
                              void* d_out, int out_size) {
    const float* x   = (const float*)d_in[0];
    const int*   tgt = (const int*)d_in[1];   // int32 (JAX x64 disabled)
    int n = in_sizes[1];
    int d = in_sizes[0] / n;

    bool tc_ok = (n % 128 == 0) && (d % BKE == 0) && (d / BKE >= 2) &&
                 (n <= N_MAX) && ((size_t)n * d <= (size_t)N_MAX * D_MAX);
    if (tc_ok) {
        static bool attr_set = false;
        if (!attr_set) {
            cudaFuncSetAttribute(gemm_mma_kernel,
                                 cudaFuncAttributeMaxDynamicSharedMemorySize, SM_TOTAL);
            attr_set = true;
        }
        prep_kernel<<<1 + n / 8, 256>>>(x, tgt, n, d);
        gemm_mma_kernel<<<296, 256, SM_TOTAL>>>((float*)d_out, n, d);
    } else {
        legacy_prep<<<(n + 7) / 8, 256>>>(x, tgt, n, d);
        int nb = n / LT;
        int nblocks = nb * (nb + 1) / 2;
        gemm_reduce_legacy<<<nblocks, 256>>>(x, tgt, n, d, nb);
        partial_kernel<<<NPART, 256>>>(n);
        final_kernel<<<1, 32>>>((float*)d_out, n);
    }
}